// round 10
// baseline (speedup 1.0000x reference)
#include <cuda_runtime.h>
#include <cuda_bf16.h>
#include <math.h>

// Problem constants
#define SEQ_LEN   512
#define PRED_LEN  96
#define PATCH_LEN 16
#define STRIDE    8
#define NQ        4
#define NLAYERS   3
#define NPATCH    63           // (512-16)/8+1
#define BATCH     32
#define CHANS     128
#define NCH       (BATCH*CHANS)        // 4096
#define FAN_IN    (NPATCH*NQ)          // 252
#define FPAD      256                  // head k padded to 256
#define NPAIR     136                  // 16*17/2
#define KSEG      192                  // unified k per partial block (768/4)
#define NPART     (BATCH*PRED_LEN*CHANS/2)   // 196608 ull per k-quarter

typedef unsigned long long ull;

// ---- packed f32x2 helpers (sm_103a) ---------------------------------------
__device__ __forceinline__ ull fma2(ull a, ull b, ull c) {
    ull d; asm("fma.rn.f32x2 %0, %1, %2, %3;" : "=l"(d) : "l"(a), "l"(b), "l"(c)); return d;
}
__device__ __forceinline__ ull mul2(ull a, ull b) {
    ull d; asm("mul.rn.f32x2 %0, %1, %2;" : "=l"(d) : "l"(a), "l"(b)); return d;
}
__device__ __forceinline__ ull add2(ull a, ull b) {
    ull d; asm("add.rn.f32x2 %0, %1, %2;" : "=l"(d) : "l"(a), "l"(b)); return d;
}
__device__ __forceinline__ ull pack2(float lo, float hi) {
    ull d; asm("mov.b64 %0, {%1, %2};" : "=l"(d) : "f"(lo), "f"(hi)); return d;
}
__device__ __forceinline__ float lo2(ull a) { return __uint_as_float((unsigned)(a & 0xffffffffull)); }
__device__ __forceinline__ float hi2(ull a) { return __uint_as_float((unsigned)(a >> 32)); }

// Scratch (device globals; no allocation allowed)
__device__ float d_encT[FPAD * NCH];    // enc transposed [f][n]; rows 252..255 zero (4MB)
__device__ ull   d_part[4 * NPART];     // k-quarter partial outputs (6MB)

// ---------------------------------------------------------------------------
// Kernel 1: encoder. 128-thread blocks, 2 channels/thread (low regs -> high
// occupancy). Per-block prologue builds the quadratic forms in shared.
// ---------------------------------------------------------------------------
__global__ __launch_bounds__(128, 8) void enc_kernel(const float* __restrict__ x,
                                                     const float* __restrict__ weights) {
    __shared__ float2 sG[12][4];
    __shared__ float2 sU[16][16];
    __shared__ ulonglong2 sM[NPAIR * 2];

    int tid = threadIdx.x;                    // 0..127
    int gtid = blockIdx.x * 128 + tid;        // 1008 blocks * 128 = 129024 threads

    // zero the 4 pad rows of encT (rows 252..255 = 8192 ull)
    if (gtid < 8192)
        ((ull*)(d_encT + (size_t)FAN_IN * NCH))[gtid] = 0ULL;

    if (tid < 12) {
        float phi   = weights[tid*3 + 0];
        float theta = weights[tid*3 + 1];
        float omega = weights[tid*3 + 2];
        float ct = cosf(0.5f*theta), st = sinf(0.5f*theta);
        float ap = 0.5f*(phi + omega);
        float am = 0.5f*(phi - omega);
        float cap = cosf(ap), sap = sinf(ap);
        float cam = cosf(am), sam = sinf(am);
        sG[tid][0] = make_float2( cap*ct, -sap*ct);
        sG[tid][1] = make_float2(-cam*st, -sam*st);
        sG[tid][2] = make_float2( cam*st, -sam*st);
        sG[tid][3] = make_float2( cap*ct,  sap*ct);
    }
    __syncthreads();

    if (tid < 16) {
        const int c = tid;
        float2 col[16];
        #pragma unroll
        for (int k = 0; k < 16; k++) col[k] = make_float2(k == c ? 1.f : 0.f, 0.f);

        #pragma unroll
        for (int l = 0; l < NLAYERS; l++) {
            #pragma unroll
            for (int w = 0; w < NQ; w++) {
                float2 m00 = sG[l*NQ + w][0], m01 = sG[l*NQ + w][1];
                float2 m10 = sG[l*NQ + w][2], m11 = sG[l*NQ + w][3];
                int bit = 1 << (3 - w);
                #pragma unroll
                for (int k0 = 0; k0 < 16; k0++) {
                    if (k0 & bit) continue;
                    int k1 = k0 | bit;
                    float2 a = col[k0], b = col[k1];
                    col[k0] = make_float2(m00.x*a.x - m00.y*a.y + m01.x*b.x - m01.y*b.y,
                                          m00.x*a.y + m00.y*a.x + m01.x*b.y + m01.y*b.x);
                    col[k1] = make_float2(m10.x*a.x - m10.y*a.y + m11.x*b.x - m11.y*b.y,
                                          m10.x*a.y + m10.y*a.x + m11.x*b.y + m11.y*b.x);
                }
            }
            int r = (l % (NQ - 1)) + 1;
            #pragma unroll
            for (int w = 0; w < NQ; w++) {
                int cb = 1 << (3 - w);
                int tb = 1 << (3 - ((w + r) & 3));
                #pragma unroll
                for (int k = 0; k < 16; k++) {
                    if ((k & cb) && !(k & tb)) {
                        float2 t = col[k]; col[k] = col[k | tb]; col[k | tb] = t;
                    }
                }
            }
        }
        #pragma unroll
        for (int k = 0; k < 16; k++) sU[k][c] = col[k];
    }
    __syncthreads();

    for (int pp = tid; pp < NPAIR; pp += 128) {
        int a = 0, rem = pp;
        while (rem >= 16 - a) { rem -= 16 - a; a++; }
        int b = a + rem;

        float s[4] = {0.f, 0.f, 0.f, 0.f};
        #pragma unroll
        for (int k = 0; k < 16; k++) {
            float2 ua = sU[k][a], ub = sU[k][b];
            float re = ua.x*ub.x + ua.y*ub.y;
            #pragma unroll
            for (int i = 0; i < 4; i++)
                s[i] += ((k >> (3 - i)) & 1) ? -re : re;
        }
        float scale = (a == b) ? 1.f : 2.f;
        ulonglong2 q0, q1;
        q0.x = pack2(s[0]*scale, s[0]*scale); q0.y = pack2(s[1]*scale, s[1]*scale);
        q1.x = pack2(s[2]*scale, s[2]*scale); q1.y = pack2(s[3]*scale, s[3]*scale);
        sM[pp*2 + 0] = q0;
        sM[pp*2 + 1] = q1;
    }
    __syncthreads();

    // ---- main: quadratic forms, 2 channels per thread ----
    int h = gtid & 2047;                   // channel-pair index within patch
    int j = gtid >> 11;                    // patch
    int n0 = h << 1;
    int b  = n0 >> 7;
    int m  = n0 & 127;

    const ull* xp = (const ull*)(x + (size_t)b * (SEQ_LEN*CHANS)
                                   + (size_t)(j*STRIDE) * CHANS + m);
    const ull EPS2 = 0x358637bd358637bdULL;   // (1e-6f, 1e-6f)

    ull v[16];
    #pragma unroll
    for (int k = 0; k < 16; k++)
        v[k] = add2(__ldg(xp + k * (CHANS/2)), EPS2);

    ull z0 = 0ULL, z1 = 0ULL, z2 = 0ULL, z3 = 0ULL, nrm2 = 0ULL;
    int p = 0;
    #pragma unroll
    for (int a = 0; a < 16; a++) {
        #pragma unroll
        for (int bb = a; bb < 16; bb++) {
            ull u = mul2(v[a], v[bb]);
            if (bb == a) nrm2 = add2(nrm2, u);
            ulonglong2 q0 = sM[2*p + 0];
            ulonglong2 q1 = sM[2*p + 1];
            z0 = fma2(u, q0.x, z0);
            z1 = fma2(u, q0.y, z1);
            z2 = fma2(u, q1.x, z2);
            z3 = fma2(u, q1.y, z3);
            p++;
        }
    }
    ull inv2 = pack2(1.0f / lo2(nrm2), 1.0f / hi2(nrm2));

    ull* e = (ull*)(d_encT + (size_t)(j*4) * NCH + n0);
    e[0*(NCH/2)] = mul2(z0, inv2);
    e[1*(NCH/2)] = mul2(z1, inv2);
    e[2*(NCH/2)] = mul2(z2, inv2);
    e[3*(NCH/2)] = mul2(z3, inv2);
}

// ---------------------------------------------------------------------------
// GEMM segment: compile-time stride (immediate-offset LDG, 1 IADD per chunk).
// Per k: 2 LDG.64 + 4 broadcast LDS.128 + 16 FFMA2 => 32 MACs.
// ---------------------------------------------------------------------------
template<int STRIDE_ULL>
__device__ __forceinline__ void gemm_seg(const ull* __restrict__ p, int nchunks,
                                         const ulonglong2* __restrict__ sw,
                                         ull acc[2][8]) {
    #pragma unroll 1
    for (int c = 0; c < nchunks; c++) {
        ull v0[4], v1[4];
        #pragma unroll
        for (int i = 0; i < 4; i++) {
            v0[i] = __ldg(p + i * STRIDE_ULL);
            v1[i] = __ldg(p + i * STRIDE_ULL + 32);
        }
        #pragma unroll
        for (int i = 0; i < 4; i++) {
            #pragma unroll
            for (int j = 0; j < 4; j++) {
                ulonglong2 q = sw[i*4 + j];
                acc[0][2*j]   = fma2(v0[i], q.x, acc[0][2*j]);
                acc[0][2*j+1] = fma2(v0[i], q.y, acc[0][2*j+1]);
                acc[1][2*j]   = fma2(v1[i], q.x, acc[1][2*j]);
                acc[1][2*j+1] = fma2(v1[i], q.y, acc[1][2*j+1]);
            }
        }
        p  += 4 * STRIDE_ULL;
        sw += 16;
    }
}

// ---------------------------------------------------------------------------
// Kernel 2: partial fused GEMM over one k-quarter of the unified k-space
// [0,768) = head-padded[0,256) ++ skip[0,512).  (UNCHANGED from round 9.)
// ---------------------------------------------------------------------------
#define OPB 8
__global__ __launch_bounds__(256, 4) void out_partial(
    const float* __restrict__ x,
    const float* __restrict__ head_w, const float* __restrict__ skip_w)
{
    __shared__ ull sS[64 * 65];            // 33.3KB; first 1536 = staged weights

    int tid = threadIdx.x;
    int cpg = tid & 31;
    int g   = tid >> 5;                    // 0..7
    int b   = blockIdx.y;
    int o0  = blockIdx.x * OPB;
    int kq  = blockIdx.z;

    #pragma unroll
    for (int it = 0; it < 6; it++) {
        int idx = it * 256 + tid;          // < 1536
        int r  = idx / KSEG;
        int kk = idx - r * KSEG;
        int k  = kq * KSEG + kk;           // unified k
        float w;
        if (k < FPAD) w = (k < FAN_IN) ? head_w[(o0 + r) * FAN_IN + k] : 0.f;
        else          w = skip_w[(o0 + r) * SEQ_LEN + (k - FPAD)];
        sS[kk * 8 + r] = pack2(w, w);
    }
    __syncthreads();

    ull acc[2][8];
    #pragma unroll
    for (int s = 0; s < 2; s++)
        #pragma unroll
        for (int r = 0; r < 8; r++) acc[s][r] = 0ULL;

    int k0u = kq * KSEG + g * 24;
    const ulonglong2* sw = (const ulonglong2*)sS + (g * 24) * 4;

    int hk = FPAD - k0u;
    hk = hk < 0 ? 0 : (hk > 24 ? 24 : hk);
    int ch = hk >> 2;

    if (ch > 0) {
        const ull* ep = (const ull*)d_encT + (size_t)k0u * (NCH/2) + b * (CHANS/2) + cpg;
        gemm_seg<NCH/2>(ep, ch, sw, acc);
    }
    if (ch < 6) {
        int l0 = k0u + hk - FPAD;
        const ull* xp = (const ull*)x + ((size_t)b * SEQ_LEN + l0) * (CHANS/2) + cpg;
        gemm_seg<CHANS/2>(xp, 6 - ch, sw + hk * 4, acc);
    }

    __syncthreads();
    #pragma unroll
    for (int s = 0; s < 2; s++) {
        int cp = cpg + 32 * s;
        #pragma unroll
        for (int r = 0; r < 8; r++)
            sS[cp * 65 + g * 8 + r] = acc[s][r];
    }
    __syncthreads();

    int cp = tid & 63;
    int q  = tid >> 6;
    #pragma unroll
    for (int t = 0; t < 2; t++) {
        int oo = 2 * q + t;
        ull s = 0ULL;
        #pragma unroll
        for (int gg = 0; gg < 8; gg++)
            s = add2(s, sS[cp * 65 + gg * 8 + oo]);
        d_part[(size_t)kq * NPART + (((size_t)b * PRED_LEN + o0 + oo) * (CHANS/2) + cp)] = s;
    }
}

// ---------------------------------------------------------------------------
// Kernel 3: reduce 4 k-quarter partials + bias -> out.
// ---------------------------------------------------------------------------
__global__ __launch_bounds__(256) void out_reduce(
    const float* __restrict__ head_b, const float* __restrict__ skip_b,
    float* __restrict__ out)
{
    int idx = blockIdx.x * 256 + threadIdx.x;     // [0, NPART)
    int o = (idx >> 6) % PRED_LEN;
    ull s = add2(add2(__ldg(d_part + idx),             __ldg(d_part + idx + NPART)),
                 add2(__ldg(d_part + idx + 2*NPART),   __ldg(d_part + idx + 3*NPART)));
    float bias = head_b[o] + skip_b[o];
    ((ull*)out)[idx] = add2(s, pack2(bias, bias));
}

// ---------------------------------------------------------------------------
extern "C" void kernel_launch(void* const* d_in, const int* in_sizes, int n_in,
                              void* d_out, int out_size) {
    const float* x       = (const float*)d_in[0];
    const float* weights = (const float*)d_in[1];
    const float* head_w  = (const float*)d_in[2];
    const float* head_b  = (const float*)d_in[3];
    const float* skip_w  = (const float*)d_in[4];
    const float* skip_b  = (const float*)d_in[5];
    float* out = (float*)d_out;

    enc_kernel<<<(NPATCH * NCH / 2) / 128, 128>>>(x, weights);
    out_partial<<<dim3(PRED_LEN / OPB, BATCH, 4), 256>>>(x, head_w, skip_w);
    out_reduce<<<NPART / 256, 256>>>(head_b, skip_b, out);
}

// round 11
// speedup vs baseline: 1.0193x; 1.0193x over previous
#include <cuda_runtime.h>
#include <cuda_bf16.h>
#include <math.h>

// Problem constants
#define SEQ_LEN   512
#define PRED_LEN  96
#define PATCH_LEN 16
#define STRIDE    8
#define NQ        4
#define NLAYERS   3
#define NPATCH    63           // (512-16)/8+1
#define BATCH     32
#define CHANS     128
#define NCH       (BATCH*CHANS)        // 4096
#define FAN_IN    (NPATCH*NQ)          // 252
#define FPAD      256                  // head k padded to 256
#define NPAIR     136                  // 16*17/2
#define NPART     (BATCH*PRED_LEN*CHANS/2)   // 196608 ull per partial
#define ENC_BLOCKS 1008                // (63*4096/2)/128
#define SKIP_BLOCKS (12*32*2)          // 768: (o-tile, batch, k-half)

typedef unsigned long long ull;

// ---- packed f32x2 helpers (sm_103a) ---------------------------------------
__device__ __forceinline__ ull fma2(ull a, ull b, ull c) {
    ull d; asm("fma.rn.f32x2 %0, %1, %2, %3;" : "=l"(d) : "l"(a), "l"(b), "l"(c)); return d;
}
__device__ __forceinline__ ull mul2(ull a, ull b) {
    ull d; asm("mul.rn.f32x2 %0, %1, %2;" : "=l"(d) : "l"(a), "l"(b)); return d;
}
__device__ __forceinline__ ull add2(ull a, ull b) {
    ull d; asm("add.rn.f32x2 %0, %1, %2;" : "=l"(d) : "l"(a), "l"(b)); return d;
}
__device__ __forceinline__ ull pack2(float lo, float hi) {
    ull d; asm("mov.b64 %0, {%1, %2};" : "=l"(d) : "f"(lo), "f"(hi)); return d;
}
__device__ __forceinline__ float lo2(ull a) { return __uint_as_float((unsigned)(a & 0xffffffffull)); }
__device__ __forceinline__ float hi2(ull a) { return __uint_as_float((unsigned)(a >> 32)); }

// Scratch (device globals; no allocation allowed)
__device__ float d_encT[FPAD * NCH];    // enc transposed [f][n]; rows 252..255 zero (4MB)
__device__ ull   d_part[4 * NPART];     // partials: 0,1 = head halves; 2,3 = skip halves

// ---------------------------------------------------------------------------
// GEMM segment: compile-time stride. Per k: 2 LDG.64 + 4 LDS.128 + 16 FFMA2.
// ---------------------------------------------------------------------------
template<int STRIDE_ULL>
__device__ __forceinline__ void gemm_seg(const ull* __restrict__ p, int nchunks,
                                         const ulonglong2* __restrict__ sw,
                                         ull acc[2][8]) {
    #pragma unroll 1
    for (int c = 0; c < nchunks; c++) {
        ull v0[4], v1[4];
        #pragma unroll
        for (int i = 0; i < 4; i++) {
            v0[i] = __ldg(p + i * STRIDE_ULL);
            v1[i] = __ldg(p + i * STRIDE_ULL + 32);
        }
        #pragma unroll
        for (int i = 0; i < 4; i++) {
            #pragma unroll
            for (int j = 0; j < 4; j++) {
                ulonglong2 q = sw[i*4 + j];
                acc[0][2*j]   = fma2(v0[i], q.x, acc[0][2*j]);
                acc[0][2*j+1] = fma2(v0[i], q.y, acc[0][2*j+1]);
                acc[1][2*j]   = fma2(v1[i], q.x, acc[1][2*j]);
                acc[1][2*j+1] = fma2(v1[i], q.y, acc[1][2*j+1]);
            }
        }
        p  += 4 * STRIDE_ULL;
        sw += 16;
    }
}

// Shared 8-way/4-way partial writer: in-block k reduction then d_part store.
// g in [0,4), 128 threads, sR stride 33.
__device__ __forceinline__ void reduce_store(ull* sR, ull acc[2][8],
                                             int tid, int cpg, int g,
                                             int b, int o0, int part_q) {
    __syncthreads();
    #pragma unroll
    for (int s = 0; s < 2; s++) {
        int cp = cpg + 32 * s;
        #pragma unroll
        for (int r = 0; r < 8; r++)
            sR[cp * 33 + g * 8 + r] = acc[s][r];
    }
    __syncthreads();
    int cp = tid & 63;
    int q  = tid >> 6;                 // 0..1
    #pragma unroll
    for (int t = 0; t < 4; t++) {
        int oo = 4 * q + t;
        ull s = add2(add2(sR[cp*33 + 0*8 + oo], sR[cp*33 + 1*8 + oo]),
                     add2(sR[cp*33 + 2*8 + oo], sR[cp*33 + 3*8 + oo]));
        d_part[(size_t)part_q * NPART + (((size_t)b * PRED_LEN + o0 + oo) * (CHANS/2) + cp)] = s;
    }
}

// ---------------------------------------------------------------------------
// Kernel A: heterogeneous fused launch.
//   blocks [0, 1008): encoder (identical math to round-9/10 passing kernels)
//   blocks [1008, 1776): skip-GEMM partials (independent of encoder!)
// ---------------------------------------------------------------------------
__global__ __launch_bounds__(128, 8) void fused_enc_skip(
    const float* __restrict__ x,
    const float* __restrict__ weights,
    const float* __restrict__ skip_w)
{
    __shared__ float2 sG[12][4];
    __shared__ float2 sU[16][16];
    __shared__ ulonglong2 sM[NPAIR * 2];
    __shared__ ull sS[64 * 33];            // 16.5KB: skip stage (2048) / reduce (2112)

    int tid = threadIdx.x;                 // 0..127

    if (blockIdx.x >= ENC_BLOCKS) {
        // =================== SKIP-GEMM PARTIAL ===================
        int sbid = blockIdx.x - ENC_BLOCKS;
        int ot   = sbid % 12;
        int b    = (sbid / 12) % BATCH;
        int half = sbid / (12 * BATCH);    // 0..1
        int o0   = ot * 8;
        int lb   = half * 256;             // skip k base

        // stage 256 k x 8 outputs, dup-packed
        #pragma unroll
        for (int it = 0; it < 16; it++) {
            int idx = it * 128 + tid;      // < 2048
            int r  = idx >> 8;
            int kk = idx & 255;
            float w = skip_w[(o0 + r) * SEQ_LEN + lb + kk];
            sS[kk * 8 + r] = pack2(w, w);
        }
        __syncthreads();

        int cpg = tid & 31;
        int g   = tid >> 5;                // 0..3, each handles 64 k = 16 chunks

        ull acc[2][8];
        #pragma unroll
        for (int s = 0; s < 2; s++)
            #pragma unroll
            for (int r = 0; r < 8; r++) acc[s][r] = 0ULL;

        const ull* xp = (const ull*)x + ((size_t)b * SEQ_LEN + lb + g * 64) * (CHANS/2) + cpg;
        gemm_seg<CHANS/2>(xp, 16, (const ulonglong2*)sS + (g * 64) * 4, acc);

        reduce_store(sS, acc, tid, cpg, g, b, o0, 2 + half);
        return;
    }

    // ======================= ENCODER =======================
    int gtid = blockIdx.x * 128 + tid;     // < 129024

    // zero the 4 pad rows of encT (rows 252..255 = 8192 ull)
    if (gtid < 8192)
        ((ull*)(d_encT + (size_t)FAN_IN * NCH))[gtid] = 0ULL;

    if (tid < 12) {
        float phi   = weights[tid*3 + 0];
        float theta = weights[tid*3 + 1];
        float omega = weights[tid*3 + 2];
        float ct = cosf(0.5f*theta), st = sinf(0.5f*theta);
        float ap = 0.5f*(phi + omega);
        float am = 0.5f*(phi - omega);
        float cap = cosf(ap), sap = sinf(ap);
        float cam = cosf(am), sam = sinf(am);
        sG[tid][0] = make_float2( cap*ct, -sap*ct);
        sG[tid][1] = make_float2(-cam*st, -sam*st);
        sG[tid][2] = make_float2( cam*st, -sam*st);
        sG[tid][3] = make_float2( cap*ct,  sap*ct);
    }
    __syncthreads();

    if (tid < 16) {
        const int c = tid;
        float2 col[16];
        #pragma unroll
        for (int k = 0; k < 16; k++) col[k] = make_float2(k == c ? 1.f : 0.f, 0.f);

        #pragma unroll
        for (int l = 0; l < NLAYERS; l++) {
            #pragma unroll
            for (int w = 0; w < NQ; w++) {
                float2 m00 = sG[l*NQ + w][0], m01 = sG[l*NQ + w][1];
                float2 m10 = sG[l*NQ + w][2], m11 = sG[l*NQ + w][3];
                int bit = 1 << (3 - w);
                #pragma unroll
                for (int k0 = 0; k0 < 16; k0++) {
                    if (k0 & bit) continue;
                    int k1 = k0 | bit;
                    float2 a = col[k0], b = col[k1];
                    col[k0] = make_float2(m00.x*a.x - m00.y*a.y + m01.x*b.x - m01.y*b.y,
                                          m00.x*a.y + m00.y*a.x + m01.x*b.y + m01.y*b.x);
                    col[k1] = make_float2(m10.x*a.x - m10.y*a.y + m11.x*b.x - m11.y*b.y,
                                          m10.x*a.y + m10.y*a.x + m11.x*b.y + m11.y*b.x);
                }
            }
            int r = (l % (NQ - 1)) + 1;
            #pragma unroll
            for (int w = 0; w < NQ; w++) {
                int cb = 1 << (3 - w);
                int tb = 1 << (3 - ((w + r) & 3));
                #pragma unroll
                for (int k = 0; k < 16; k++) {
                    if ((k & cb) && !(k & tb)) {
                        float2 t = col[k]; col[k] = col[k | tb]; col[k | tb] = t;
                    }
                }
            }
        }
        #pragma unroll
        for (int k = 0; k < 16; k++) sU[k][c] = col[k];
    }
    __syncthreads();

    for (int pp = tid; pp < NPAIR; pp += 128) {
        int a = 0, rem = pp;
        while (rem >= 16 - a) { rem -= 16 - a; a++; }
        int b = a + rem;

        float s[4] = {0.f, 0.f, 0.f, 0.f};
        #pragma unroll
        for (int k = 0; k < 16; k++) {
            float2 ua = sU[k][a], ub = sU[k][b];
            float re = ua.x*ub.x + ua.y*ub.y;
            #pragma unroll
            for (int i = 0; i < 4; i++)
                s[i] += ((k >> (3 - i)) & 1) ? -re : re;
        }
        float scale = (a == b) ? 1.f : 2.f;
        ulonglong2 q0, q1;
        q0.x = pack2(s[0]*scale, s[0]*scale); q0.y = pack2(s[1]*scale, s[1]*scale);
        q1.x = pack2(s[2]*scale, s[2]*scale); q1.y = pack2(s[3]*scale, s[3]*scale);
        sM[pp*2 + 0] = q0;
        sM[pp*2 + 1] = q1;
    }
    __syncthreads();

    int h = gtid & 2047;
    int j = gtid >> 11;
    int n0 = h << 1;
    int b  = n0 >> 7;
    int m  = n0 & 127;

    const ull* xp = (const ull*)(x + (size_t)b * (SEQ_LEN*CHANS)
                                   + (size_t)(j*STRIDE) * CHANS + m);
    const ull EPS2 = 0x358637bd358637bdULL;   // (1e-6f, 1e-6f)

    ull v[16];
    #pragma unroll
    for (int k = 0; k < 16; k++)
        v[k] = add2(__ldg(xp + k * (CHANS/2)), EPS2);

    ull z0 = 0ULL, z1 = 0ULL, z2 = 0ULL, z3 = 0ULL, nrm2 = 0ULL;
    int p = 0;
    #pragma unroll
    for (int a = 0; a < 16; a++) {
        #pragma unroll
        for (int bb = a; bb < 16; bb++) {
            ull u = mul2(v[a], v[bb]);
            if (bb == a) nrm2 = add2(nrm2, u);
            ulonglong2 q0 = sM[2*p + 0];
            ulonglong2 q1 = sM[2*p + 1];
            z0 = fma2(u, q0.x, z0);
            z1 = fma2(u, q0.y, z1);
            z2 = fma2(u, q1.x, z2);
            z3 = fma2(u, q1.y, z3);
            p++;
        }
    }
    ull inv2 = pack2(1.0f / lo2(nrm2), 1.0f / hi2(nrm2));

    ull* e = (ull*)(d_encT + (size_t)(j*4) * NCH + n0);
    e[0*(NCH/2)] = mul2(z0, inv2);
    e[1*(NCH/2)] = mul2(z1, inv2);
    e[2*(NCH/2)] = mul2(z2, inv2);
    e[3*(NCH/2)] = mul2(z3, inv2);
}

// ---------------------------------------------------------------------------
// Kernel B: head-GEMM partials over encT. grid (12, 32, 2), 128 threads.
// Each block: 128 head-k (padded space [0,256)), g-slice = 32 k = 8 chunks.
// ---------------------------------------------------------------------------
__global__ __launch_bounds__(128, 8) void head_partial(
    const float* __restrict__ head_w)
{
    __shared__ ull sS[64 * 33];            // stage (1024) / reduce (2112)

    int tid  = threadIdx.x;
    int o0   = blockIdx.x * 8;
    int b    = blockIdx.y;
    int half = blockIdx.z;                 // 0..1
    int k0   = half * 128;

    #pragma unroll
    for (int it = 0; it < 8; it++) {
        int idx = it * 128 + tid;          // < 1024
        int r  = idx >> 7;
        int kk = idx & 127;
        int k  = k0 + kk;
        float w = (k < FAN_IN) ? head_w[(o0 + r) * FAN_IN + k] : 0.f;
        sS[kk * 8 + r] = pack2(w, w);
    }
    __syncthreads();

    int cpg = tid & 31;
    int g   = tid >> 5;                    // 0..3, each 32 k = 8 chunks

    ull acc[2][8];
    #pragma unroll
    for (int s = 0; s < 2; s++)
        #pragma unroll
        for (int r = 0; r < 8; r++) acc[s][r] = 0ULL;

    const ull* ep = (const ull*)d_encT + (size_t)(k0 + g * 32) * (NCH/2) + b * (CHANS/2) + cpg;
    gemm_seg<NCH/2>(ep, 8, (const ulonglong2*)sS + (g * 32) * 4, acc);

    reduce_store(sS, acc, tid, cpg, g, b, o0, half);
}

// ---------------------------------------------------------------------------
// Kernel C: reduce 4 partials + bias -> out.
// ---------------------------------------------------------------------------
__global__ __launch_bounds__(256) void out_reduce(
    const float* __restrict__ head_b, const float* __restrict__ skip_b,
    float* __restrict__ out)
{
    int idx = blockIdx.x * 256 + threadIdx.x;     // [0, NPART)
    int o = (idx >> 6) % PRED_LEN;
    ull s = add2(add2(__ldg(d_part + idx),             __ldg(d_part + idx + NPART)),
                 add2(__ldg(d_part + idx + 2*NPART),   __ldg(d_part + idx + 3*NPART)));
    float bias = head_b[o] + skip_b[o];
    ((ull*)out)[idx] = add2(s, pack2(bias, bias));
}

// ---------------------------------------------------------------------------
extern "C" void kernel_launch(void* const* d_in, const int* in_sizes, int n_in,
                              void* d_out, int out_size) {
    const float* x       = (const float*)d_in[0];
    const float* weights = (const float*)d_in[1];
    const float* head_w  = (const float*)d_in[2];
    const float* head_b  = (const float*)d_in[3];
    const float* skip_w  = (const float*)d_in[4];
    const float* skip_b  = (const float*)d_in[5];
    float* out = (float*)d_out;

    fused_enc_skip<<<ENC_BLOCKS + SKIP_BLOCKS, 128>>>(x, weights, skip_w);
    head_partial<<<dim3(12, BATCH, 2), 128>>>(head_w);
    out_reduce<<<NPART / 256, 256>>>(head_b, skip_b, out);
}

// round 12
// speedup vs baseline: 1.0603x; 1.0402x over previous
#include <cuda_runtime.h>
#include <cuda_bf16.h>
#include <math.h>

// Problem constants
#define SEQ_LEN   512
#define PRED_LEN  96
#define PATCH_LEN 16
#define STRIDE    8
#define NQ        4
#define NLAYERS   3
#define NPATCH    63           // (512-16)/8+1
#define BATCH     32
#define CHANS     128
#define NCH       (BATCH*CHANS)        // 4096
#define FAN_IN    (NPATCH*NQ)          // 252
#define FPAD      256                  // head k padded to 256
#define NPAIR     136                  // 16*17/2
#define NPART     (BATCH*PRED_LEN*CHANS/2)   // 196608 ull per partial
#define ENC_BLOCKS 1008                // (63*4096/2)/128
#define SKIP_BLOCKS (12*32*2)          // 768: (o-tile, batch, k-half)

typedef unsigned long long ull;

// ---- packed f32x2 helpers (sm_103a) ---------------------------------------
__device__ __forceinline__ ull fma2(ull a, ull b, ull c) {
    ull d; asm("fma.rn.f32x2 %0, %1, %2, %3;" : "=l"(d) : "l"(a), "l"(b), "l"(c)); return d;
}
__device__ __forceinline__ ull mul2(ull a, ull b) {
    ull d; asm("mul.rn.f32x2 %0, %1, %2;" : "=l"(d) : "l"(a), "l"(b)); return d;
}
__device__ __forceinline__ ull add2(ull a, ull b) {
    ull d; asm("add.rn.f32x2 %0, %1, %2;" : "=l"(d) : "l"(a), "l"(b)); return d;
}
__device__ __forceinline__ ull pack2(float lo, float hi) {
    ull d; asm("mov.b64 %0, {%1, %2};" : "=l"(d) : "f"(lo), "f"(hi)); return d;
}
__device__ __forceinline__ float lo2(ull a) { return __uint_as_float((unsigned)(a & 0xffffffffull)); }
__device__ __forceinline__ float hi2(ull a) { return __uint_as_float((unsigned)(a >> 32)); }

// Scratch (device globals; no allocation allowed)
__device__ float d_encT[FPAD * NCH];    // enc transposed [f][n]; rows 252..255 zero (4MB)
__device__ ull   d_part[2 * NPART];     // skip-GEMM partials (two k-halves)

// ---------------------------------------------------------------------------
// GEMM segment: compile-time stride. Per k: 2 LDG.64 + 4 LDS.128 + 16 FFMA2.
// ---------------------------------------------------------------------------
template<int STRIDE_ULL>
__device__ __forceinline__ void gemm_seg(const ull* __restrict__ p, int nchunks,
                                         const ulonglong2* __restrict__ sw,
                                         ull acc[2][8]) {
    #pragma unroll 1
    for (int c = 0; c < nchunks; c++) {
        ull v0[4], v1[4];
        #pragma unroll
        for (int i = 0; i < 4; i++) {
            v0[i] = __ldg(p + i * STRIDE_ULL);
            v1[i] = __ldg(p + i * STRIDE_ULL + 32);
        }
        #pragma unroll
        for (int i = 0; i < 4; i++) {
            #pragma unroll
            for (int j = 0; j < 4; j++) {
                ulonglong2 q = sw[i*4 + j];
                acc[0][2*j]   = fma2(v0[i], q.x, acc[0][2*j]);
                acc[0][2*j+1] = fma2(v0[i], q.y, acc[0][2*j+1]);
                acc[1][2*j]   = fma2(v1[i], q.x, acc[1][2*j]);
                acc[1][2*j+1] = fma2(v1[i], q.y, acc[1][2*j+1]);
            }
        }
        p  += 4 * STRIDE_ULL;
        sw += 16;
    }
}

// 4-group in-block k reduction then d_part store (128-thr blocks, stride 33).
__device__ __forceinline__ void reduce_store(ull* sR, ull acc[2][8],
                                             int tid, int cpg, int g,
                                             int b, int o0, int part_q) {
    __syncthreads();
    #pragma unroll
    for (int s = 0; s < 2; s++) {
        int cp = cpg + 32 * s;
        #pragma unroll
        for (int r = 0; r < 8; r++)
            sR[cp * 33 + g * 8 + r] = acc[s][r];
    }
    __syncthreads();
    int cp = tid & 63;
    int q  = tid >> 6;                 // 0..1
    #pragma unroll
    for (int t = 0; t < 4; t++) {
        int oo = 4 * q + t;
        ull s = add2(add2(sR[cp*33 + 0*8 + oo], sR[cp*33 + 1*8 + oo]),
                     add2(sR[cp*33 + 2*8 + oo], sR[cp*33 + 3*8 + oo]));
        d_part[(size_t)part_q * NPART + (((size_t)b * PRED_LEN + o0 + oo) * (CHANS/2) + cp)] = s;
    }
}

// ---------------------------------------------------------------------------
// Kernel A: heterogeneous fused launch.
//   blocks [0, 1008): encoder; blocks [1008, 1776): skip-GEMM partials.
// ---------------------------------------------------------------------------
__global__ __launch_bounds__(128, 8) void fused_enc_skip(
    const float* __restrict__ x,
    const float* __restrict__ weights,
    const float* __restrict__ skip_w)
{
    __shared__ float2 sG[12][4];
    __shared__ float2 sU[16][16];
    __shared__ ulonglong2 sM[NPAIR * 2];
    __shared__ ull sS[64 * 33];            // 16.5KB: skip stage (2048) / reduce (2112)

    int tid = threadIdx.x;                 // 0..127

    if (blockIdx.x >= ENC_BLOCKS) {
        // =================== SKIP-GEMM PARTIAL ===================
        int sbid = blockIdx.x - ENC_BLOCKS;
        int ot   = sbid % 12;
        int b    = (sbid / 12) % BATCH;
        int half = sbid / (12 * BATCH);    // 0..1
        int o0   = ot * 8;
        int lb   = half * 256;             // skip k base

        #pragma unroll
        for (int it = 0; it < 16; it++) {
            int idx = it * 128 + tid;      // < 2048
            int r  = idx >> 8;
            int kk = idx & 255;
            float w = skip_w[(o0 + r) * SEQ_LEN + lb + kk];
            sS[kk * 8 + r] = pack2(w, w);
        }
        __syncthreads();

        int cpg = tid & 31;
        int g   = tid >> 5;                // 0..3, each 64 k = 16 chunks

        ull acc[2][8];
        #pragma unroll
        for (int s = 0; s < 2; s++)
            #pragma unroll
            for (int r = 0; r < 8; r++) acc[s][r] = 0ULL;

        const ull* xp = (const ull*)x + ((size_t)b * SEQ_LEN + lb + g * 64) * (CHANS/2) + cpg;
        gemm_seg<CHANS/2>(xp, 16, (const ulonglong2*)sS + (g * 64) * 4, acc);

        reduce_store(sS, acc, tid, cpg, g, b, o0, half);
        return;
    }

    // ======================= ENCODER =======================
    int gtid = blockIdx.x * 128 + tid;     // < 129024

    // zero the 4 pad rows of encT (rows 252..255 = 8192 ull)
    if (gtid < 8192)
        ((ull*)(d_encT + (size_t)FAN_IN * NCH))[gtid] = 0ULL;

    if (tid < 12) {
        float phi   = weights[tid*3 + 0];
        float theta = weights[tid*3 + 1];
        float omega = weights[tid*3 + 2];
        float ct = cosf(0.5f*theta), st = sinf(0.5f*theta);
        float ap = 0.5f*(phi + omega);
        float am = 0.5f*(phi - omega);
        float cap = cosf(ap), sap = sinf(ap);
        float cam = cosf(am), sam = sinf(am);
        sG[tid][0] = make_float2( cap*ct, -sap*ct);
        sG[tid][1] = make_float2(-cam*st, -sam*st);
        sG[tid][2] = make_float2( cam*st, -sam*st);
        sG[tid][3] = make_float2( cap*ct,  sap*ct);
    }
    __syncthreads();

    if (tid < 16) {
        const int c = tid;
        float2 col[16];
        #pragma unroll
        for (int k = 0; k < 16; k++) col[k] = make_float2(k == c ? 1.f : 0.f, 0.f);

        #pragma unroll
        for (int l = 0; l < NLAYERS; l++) {
            #pragma unroll
            for (int w = 0; w < NQ; w++) {
                float2 m00 = sG[l*NQ + w][0], m01 = sG[l*NQ + w][1];
                float2 m10 = sG[l*NQ + w][2], m11 = sG[l*NQ + w][3];
                int bit = 1 << (3 - w);
                #pragma unroll
                for (int k0 = 0; k0 < 16; k0++) {
                    if (k0 & bit) continue;
                    int k1 = k0 | bit;
                    float2 a = col[k0], b = col[k1];
                    col[k0] = make_float2(m00.x*a.x - m00.y*a.y + m01.x*b.x - m01.y*b.y,
                                          m00.x*a.y + m00.y*a.x + m01.x*b.y + m01.y*b.x);
                    col[k1] = make_float2(m10.x*a.x - m10.y*a.y + m11.x*b.x - m11.y*b.y,
                                          m10.x*a.y + m10.y*a.x + m11.x*b.y + m11.y*b.x);
                }
            }
            int r = (l % (NQ - 1)) + 1;
            #pragma unroll
            for (int w = 0; w < NQ; w++) {
                int cb = 1 << (3 - w);
                int tb = 1 << (3 - ((w + r) & 3));
                #pragma unroll
                for (int k = 0; k < 16; k++) {
                    if ((k & cb) && !(k & tb)) {
                        float2 t = col[k]; col[k] = col[k | tb]; col[k | tb] = t;
                    }
                }
            }
        }
        #pragma unroll
        for (int k = 0; k < 16; k++) sU[k][c] = col[k];
    }
    __syncthreads();

    for (int pp = tid; pp < NPAIR; pp += 128) {
        int a = 0, rem = pp;
        while (rem >= 16 - a) { rem -= 16 - a; a++; }
        int b = a + rem;

        float s[4] = {0.f, 0.f, 0.f, 0.f};
        #pragma unroll
        for (int k = 0; k < 16; k++) {
            float2 ua = sU[k][a], ub = sU[k][b];
            float re = ua.x*ub.x + ua.y*ub.y;
            #pragma unroll
            for (int i = 0; i < 4; i++)
                s[i] += ((k >> (3 - i)) & 1) ? -re : re;
        }
        float scale = (a == b) ? 1.f : 2.f;
        ulonglong2 q0, q1;
        q0.x = pack2(s[0]*scale, s[0]*scale); q0.y = pack2(s[1]*scale, s[1]*scale);
        q1.x = pack2(s[2]*scale, s[2]*scale); q1.y = pack2(s[3]*scale, s[3]*scale);
        sM[pp*2 + 0] = q0;
        sM[pp*2 + 1] = q1;
    }
    __syncthreads();

    int h = gtid & 2047;
    int j = gtid >> 11;
    int n0 = h << 1;
    int b  = n0 >> 7;
    int m  = n0 & 127;

    const ull* xp = (const ull*)(x + (size_t)b * (SEQ_LEN*CHANS)
                                   + (size_t)(j*STRIDE) * CHANS + m);
    const ull EPS2 = 0x358637bd358637bdULL;   // (1e-6f, 1e-6f)

    ull v[16];
    #pragma unroll
    for (int k = 0; k < 16; k++)
        v[k] = add2(__ldg(xp + k * (CHANS/2)), EPS2);

    ull z0 = 0ULL, z1 = 0ULL, z2 = 0ULL, z3 = 0ULL, nrm2 = 0ULL;
    int p = 0;
    #pragma unroll
    for (int a = 0; a < 16; a++) {
        #pragma unroll
        for (int bb = a; bb < 16; bb++) {
            ull u = mul2(v[a], v[bb]);
            if (bb == a) nrm2 = add2(nrm2, u);
            ulonglong2 q0 = sM[2*p + 0];
            ulonglong2 q1 = sM[2*p + 1];
            z0 = fma2(u, q0.x, z0);
            z1 = fma2(u, q0.y, z1);
            z2 = fma2(u, q1.x, z2);
            z3 = fma2(u, q1.y, z3);
            p++;
        }
    }
    ull inv2 = pack2(1.0f / lo2(nrm2), 1.0f / hi2(nrm2));

    ull* e = (ull*)(d_encT + (size_t)(j*4) * NCH + n0);
    e[0*(NCH/2)] = mul2(z0, inv2);
    e[1*(NCH/2)] = mul2(z1, inv2);
    e[2*(NCH/2)] = mul2(z2, inv2);
    e[3*(NCH/2)] = mul2(z3, inv2);
}

// ---------------------------------------------------------------------------
// Kernel B: head-GEMM over encT + final combine (skip partials + bias) -> out.
// grid (12, 32), 256 threads: cpg=tid&31, g=tid>>5 (8 slices x 32 k = 256 k).
// In-block 8-way reduction (stride 65), then epilogue reads d_part[0..1].
// ---------------------------------------------------------------------------
__global__ __launch_bounds__(256, 4) void head_final(
    const float* __restrict__ head_w,
    const float* __restrict__ head_b, const float* __restrict__ skip_b,
    float* __restrict__ out)
{
    __shared__ ull sS[64 * 65];            // 33.3KB: stage (2048) / reduce (4160)

    int tid = threadIdx.x;                 // 0..255
    int o0  = blockIdx.x * 8;
    int b   = blockIdx.y;

    // stage 256 padded head-k x 8 outputs, dup-packed
    #pragma unroll
    for (int it = 0; it < 8; it++) {
        int idx = it * 256 + tid;          // < 2048
        int r  = idx >> 8;
        int kk = idx & 255;
        float w = (kk < FAN_IN) ? head_w[(o0 + r) * FAN_IN + kk] : 0.f;
        sS[kk * 8 + r] = pack2(w, w);
    }
    __syncthreads();

    int cpg = tid & 31;
    int g   = tid >> 5;                    // 0..7, each 32 k = 8 chunks

    ull acc[2][8];
    #pragma unroll
    for (int s = 0; s < 2; s++)
        #pragma unroll
        for (int r = 0; r < 8; r++) acc[s][r] = 0ULL;

    const ull* ep = (const ull*)d_encT + (size_t)(g * 32) * (NCH/2) + b * (CHANS/2) + cpg;
    gemm_seg<NCH/2>(ep, 8, (const ulonglong2*)sS + (g * 32) * 4, acc);

    // 8-way k reduction (stride 65)
    __syncthreads();
    #pragma unroll
    for (int s = 0; s < 2; s++) {
        int cp = cpg + 32 * s;
        #pragma unroll
        for (int r = 0; r < 8; r++)
            sS[cp * 65 + g * 8 + r] = acc[s][r];
    }
    __syncthreads();

    int cp = tid & 63;
    int q  = tid >> 6;                     // 0..3
    #pragma unroll
    for (int t = 0; t < 2; t++) {
        int oo = 2 * q + t;
        ull s = 0ULL;
        #pragma unroll
        for (int gg = 0; gg < 8; gg++)
            s = add2(s, sS[cp * 65 + gg * 8 + oo]);
        size_t oidx = ((size_t)b * PRED_LEN + o0 + oo) * (CHANS/2) + cp;
        s = add2(s, add2(__ldg(d_part + oidx), __ldg(d_part + NPART + oidx)));
        float bias = head_b[o0 + oo] + skip_b[o0 + oo];
        s = add2(s, pack2(bias, bias));
        ((ull*)out)[oidx] = s;
    }
}

// ---------------------------------------------------------------------------
extern "C" void kernel_launch(void* const* d_in, const int* in_sizes, int n_in,
                              void* d_out, int out_size) {
    const float* x       = (const float*)d_in[0];
    const float* weights = (const float*)d_in[1];
    const float* head_w  = (const float*)d_in[2];
    const float* head_b  = (const float*)d_in[3];
    const float* skip_w  = (const float*)d_in[4];
    const float* skip_b  = (const float*)d_in[5];
    float* out = (float*)d_out;

    fused_enc_skip<<<ENC_BLOCKS + SKIP_BLOCKS, 128>>>(x, weights, skip_w);
    head_final<<<dim3(12, BATCH), 256>>>(head_w, head_b, skip_b, out);
}